// round 6
// baseline (speedup 1.0000x reference)
#include <cuda_runtime.h>
#include <math.h>

typedef unsigned long long ull;

// Shapes
#define NROWS 4096
#define XLD   1184   // padded 1182 -> 1184 (news[1024] | price[158] | 2 zeros)
#define NT    74     // 1184 / 16 k-tiles
#define RPB   16     // rows per k_main block
#define OFF_PRED 0
#define OFF_RW1  (NROWS)
#define OFF_HID  (NROWS + NROWS*64)
#define OFF_TK   (NROWS + 2*NROWS*64)
#define OFF_RW2  (NROWS + 2*NROWS*64 + NROWS*2)

// Scratch
__device__ float g_X[(size_t)NROWS * XLD];
__device__ float g_W2[(size_t)XLD * 128];   // remapped+padded router_W

// ---------------------------------------------------------------------------
// f32x2 helpers (FFMA2 reachable only via PTX)
// ---------------------------------------------------------------------------
__device__ __forceinline__ ull pk2(float v) {
    ull r; asm("mov.b64 %0, {%1,%1};" : "=l"(r) : "f"(v)); return r;
}
__device__ __forceinline__ void fma2(ull& d, ull a, ull b) {
    asm("fma.rn.f32x2 %0, %1, %2, %0;" : "+l"(d) : "l"(a), "l"(b));
}
__device__ __forceinline__ void unpk2(ull v, float& lo, float& hi) {
    asm("mov.b64 {%0,%1}, %2;" : "=f"(lo), "=f"(hi) : "l"(v));
}
union F4U { float4 f; ull u[2]; };

// ---------------------------------------------------------------------------
// Kernel 1: masked news aggregation + price mean -> g_X.
// Blocks >= NROWS additionally remap router_W into g_W2 (replaces k_prep;
// same-stream ordering guarantees g_W2 ready before k_main).
// ---------------------------------------------------------------------------
__global__ __launch_bounds__(256) void k_agg(const float* __restrict__ price,
                                             const float* __restrict__ news,
                                             const float* __restrict__ mask,
                                             const float* __restrict__ rW)
{
    int n   = blockIdx.x;
    int tid = threadIdx.x;
    if (n >= NROWS) {                       // W remap blocks
        int idx = (n - NROWS) * 256 + tid;  // over 1184*128
        int k = idx >> 7, c = idx & 127;
        float v = 0.f;
        if (k < 1182) {
            int wr = (k < 1024) ? (k + 158) : (k - 1024);
            v = __ldg(rW + (size_t)wr * 128 + c);
        }
        g_W2[idx] = v;
        return;
    }

    const float* nf   = news  + (size_t)n * 32 * 1024 + tid * 4;
    const float* pf   = price + (size_t)n * 32 * 158;
    const float* mrow = mask  + n * 32;

    float4 acc = make_float4(0.f, 0.f, 0.f, 0.f);
    float msum = 0.f, pacc = 0.f;

#pragma unroll 8
    for (int t = 0; t < 32; ++t) {
        float m = __ldg(mrow + t);
        msum += m;
        float4 v = *(const float4*)(nf + t * 1024);
        acc.x = fmaf(m, v.x, acc.x);
        acc.y = fmaf(m, v.y, acc.y);
        acc.z = fmaf(m, v.z, acc.z);
        acc.w = fmaf(m, v.w, acc.w);
        if (tid < 158) pacc += __ldg(pf + t * 158 + tid);
    }

    float inv = 1.f / fmaxf(msum, 1e-6f);
    float* xr = g_X + (size_t)n * XLD;
    *(float4*)(xr + tid * 4) =
        make_float4(acc.x * inv, acc.y * inv, acc.z * inv, acc.w * inv);
    if (tid < 158)       xr[1024 + tid] = pacc * (1.f / 32.f);
    else if (tid < 160)  xr[1024 + tid] = 0.f;
}

// ---------------------------------------------------------------------------
// Kernel 2: fused router GEMM (FFMA2 col-pairs, double-buffered) + gate GEMM
// + top2 routing + sparse expert path.
// 256 blocks x 256 threads, 16 rows/block, 2 CTAs/SM.
// GEMM1 warp tile: 4 rows x 64 cols; thread tile: 2 rows x 4 cols.
// ---------------------------------------------------------------------------
__global__ __launch_bounds__(256, 2) void k_main(
    const float* __restrict__ rb,
    const float* __restrict__ gW,  const float* __restrict__ gb,
    const float* __restrict__ eW,  const float* __restrict__ eb,
    const float* __restrict__ wq,  const float* __restrict__ wqb,
    const float* __restrict__ wk,  const float* __restrict__ wkb,
    const float* __restrict__ wv,  const float* __restrict__ wvb,
    const float* __restrict__ wo,  const float* __restrict__ wob,
    float* __restrict__ out)
{
    __shared__ __align__(16) float Xs[2][16][18];   // [buf][k][row] pitch 18
    __shared__ __align__(16) float Ws[2][16][128];  // [buf][k][col]
    __shared__ __align__(16) float h_s[RPB][132];   // tanh(router) outputs
    __shared__ __align__(16) float hid_s[RPB][68];  // gate outputs (hidden)

    const int tid  = threadIdx.x;
    const int row0 = blockIdx.x * RPB;
    const int wid  = tid >> 5;
    const int lane = tid & 31;

    // GEMM1 compute mapping: warp = 4 rows x 64 cols, thread = 2 rows x 4 cols
    const int xoff = (wid & 3) * 4 + (lane >> 4) * 2;   // even -> LDS.64 ok
    const int woff = (wid >> 2) * 64 + (lane & 15) * 4;

    // GEMM1 loader mapping
    const int lr  = tid >> 4;          // 0..15  (X row)
    const int lk  = tid & 15;          // 0..15  (X k within tile)
    const int wk1 = tid >> 5;          // 0..7   (W k within tile)
    const int wc4 = (tid & 31) * 4;    // 0..124 (W col)
    const float* xsrc = g_X + (size_t)(row0 + lr) * XLD + lk;

    ull acc00 = 0, acc01 = 0, acc10 = 0, acc11 = 0;

    float  xpre;
    float4 wpreA, wpreB;

    // ---- prologue: tile 0 loaded+stored, tile 1 loaded ----------------------
    xpre  = xsrc[0];
    wpreA = *(const float4*)(g_W2 + (size_t)wk1 * 128 + wc4);
    wpreB = *(const float4*)(g_W2 + (size_t)(wk1 + 8) * 128 + wc4);
    Xs[0][lk][lr] = xpre;
    *(float4*)&Ws[0][wk1][wc4]     = wpreA;
    *(float4*)&Ws[0][wk1 + 8][wc4] = wpreB;
    xpre  = xsrc[16];
    wpreA = *(const float4*)(g_W2 + (size_t)(16 + wk1) * 128 + wc4);
    wpreB = *(const float4*)(g_W2 + (size_t)(16 + wk1 + 8) * 128 + wc4);
    __syncthreads();

    // ---- main pipeline: 1 barrier / tile ------------------------------------
#pragma unroll 1
    for (int it = 0; it < NT; ++it) {
        const int cur = it & 1;
        if (it + 1 < NT) {
            Xs[1 - cur][lk][lr] = xpre;
            *(float4*)&Ws[1 - cur][wk1][wc4]     = wpreA;
            *(float4*)&Ws[1 - cur][wk1 + 8][wc4] = wpreB;
        }
        if (it + 2 < NT) {
            int kb = (it + 2) * 16;
            xpre  = xsrc[kb];
            wpreA = *(const float4*)(g_W2 + (size_t)(kb + wk1) * 128 + wc4);
            wpreB = *(const float4*)(g_W2 + (size_t)(kb + wk1 + 8) * 128 + wc4);
        }
#pragma unroll
        for (int k = 0; k < 16; ++k) {
            F4U wu;
            wu.f = *(const float4*)&Ws[cur][k][woff];       // 2 col-pairs
            float2 xv = *(const float2*)&Xs[cur][k][xoff];  // 2 rows
            ull x0 = pk2(xv.x), x1 = pk2(xv.y);
            fma2(acc00, wu.u[0], x0);
            fma2(acc01, wu.u[1], x0);
            fma2(acc10, wu.u[0], x1);
            fma2(acc11, wu.u[1], x1);
        }
        __syncthreads();
    }

    // ---- bias + tanh -> h_s  (acc[r][cp] = (col woff+2cp, col woff+2cp+1)) --
    {
        float b0 = __ldg(rb + woff),     b1 = __ldg(rb + woff + 1);
        float b2 = __ldg(rb + woff + 2), b3 = __ldg(rb + woff + 3);
        float a, b;
        unpk2(acc00, a, b);
        h_s[xoff][woff]     = tanhf(a + b0);  h_s[xoff][woff + 1] = tanhf(b + b1);
        unpk2(acc01, a, b);
        h_s[xoff][woff + 2] = tanhf(a + b2);  h_s[xoff][woff + 3] = tanhf(b + b3);
        unpk2(acc10, a, b);
        h_s[xoff + 1][woff]     = tanhf(a + b0);  h_s[xoff + 1][woff + 1] = tanhf(b + b1);
        unpk2(acc11, a, b);
        h_s[xoff + 1][woff + 2] = tanhf(a + b2);  h_s[xoff + 1][woff + 3] = tanhf(b + b3);
    }
    __syncthreads();

    // ---------------- GEMM2: hidden = h @ gate_W (16x64) --------------------
    {
        int r2 = tid >> 4;           // 0..15
        int j0 = (tid & 15) * 4;     // 0,4,..,60
        float ha[4];
#pragma unroll
        for (int j = 0; j < 4; ++j) ha[j] = __ldg(gb + j0 + j);
#pragma unroll 8
        for (int k = 0; k < 128; ++k) {
            float hv = h_s[r2][k];
            float4 g0 = *(const float4*)(gW + (size_t)k * 64 + j0);
            ha[0] = fmaf(hv, g0.x, ha[0]);
            ha[1] = fmaf(hv, g0.y, ha[1]);
            ha[2] = fmaf(hv, g0.z, ha[2]);
            ha[3] = fmaf(hv, g0.w, ha[3]);
        }
        int n = row0 + r2;
        float* ho = out + OFF_HID + (size_t)n * 64 + j0;
#pragma unroll
        for (int j = 0; j < 4; ++j) {
            hid_s[r2][j0 + j] = ha[j];
            ho[j] = ha[j];
        }
    }
    __syncthreads();

    // ---------------- Epilogue: top2 + routing + sparse expert path ---------
    // 8-lane groups; 16 groups needed -> threads 0..127 (warps 0..3 full).
    if (tid < 128) {
        const int L = lane & 7;
        const int r = tid >> 3;          // 0..15
        const int n = row0 + r;

        float v1 = -INFINITY, v2 = -INFINITY;
        int   i1 = 0, i2 = 0;
#pragma unroll
        for (int j = 0; j < 8; ++j) {
            int idx = L * 8 + j;
            float v = hid_s[r][idx];
            if (v > v1) { v2 = v1; i2 = i1; v1 = v; i1 = idx; }
            else if (v > v2) { v2 = v; i2 = idx; }
        }
#pragma unroll
        for (int d = 1; d <= 4; d <<= 1) {
            float b1 = __shfl_down_sync(0xffffffffu, v1, d, 8);
            int  bi1 = __shfl_down_sync(0xffffffffu, i1, d, 8);
            float b2 = __shfl_down_sync(0xffffffffu, v2, d, 8);
            int  bi2 = __shfl_down_sync(0xffffffffu, i2, d, 8);
            if (b1 > v1) {
                if (v1 >= b2) { v2 = v1; i2 = i1; }
                else          { v2 = b2; i2 = bi2; }
                v1 = b1; i1 = bi1;
            } else if (b1 > v2) {
                v2 = b1; i2 = bi1;
            }
        }
        float rw1 = 0.f, rw2 = 0.f;
        if (L == 0) {
            float e2 = expf(v2 - v1);
            float inv = 1.f / (1.f + e2);
            rw1 = inv;
            rw2 = e2 * inv;
        }
        i1  = __shfl_sync(0xffffffffu, i1, 0, 8);
        i2  = __shfl_sync(0xffffffffu, i2, 0, 8);
        rw1 = __shfl_sync(0xffffffffu, rw1, 0, 8);
        rw2 = __shfl_sync(0xffffffffu, rw2, 0, 8);

#pragma unroll
        for (int j = 0; j < 8; ++j) {
            int idx = L * 8 + j;
            float val = (idx == i1) ? rw1 : ((idx == i2) ? rw2 : 0.f);
            out[OFF_RW1 + (size_t)n * 64 + idx] = val;
            out[OFF_RW2 + (size_t)n * 64 + idx] = val;
        }
        if (L == 0) {
            out[OFF_TK + (size_t)n * 2 + 0] = (float)i1;
            out[OFF_TK + (size_t)n * 2 + 1] = (float)i2;
        }

        float pred = 0.f;
#pragma unroll
        for (int s = 0; s < 2; ++s) {
            int sel  = s ? i2 : i1;
            float rw = s ? rw2 : rw1;
            int g = sel >> 3, f = sel & 7;

            float eo = __ldg(eb + g * 8 + L);
            const float* ew = eW + (size_t)(g * 8 + L) * 64;
#pragma unroll 16
            for (int h = 0; h < 64; ++h)
                eo = fmaf(hid_s[r][h], __ldg(ew + h), eo);

            float qf = __ldg(wqb + g * 8 + L);
            float kf = __ldg(wkb + g * 8 + L);
            float vf = __ldg(wvb + g * 8 + L);
            const float* wqr = wq + (size_t)(g * 8 + L) * 8;
            const float* wkr = wk + (size_t)(g * 8 + L) * 8;
            const float* wvr = wv + (size_t)(g * 8 + L) * 8;
#pragma unroll
            for (int e = 0; e < 8; ++e) {
                float eoe = __shfl_sync(0xffffffffu, eo, e, 8);
                qf = fmaf(eoe, __ldg(wqr + e), qf);
                kf = fmaf(eoe, __ldg(wkr + e), kf);
                vf = fmaf(eoe, __ldg(wvr + e), vf);
            }
            float q8[8], k8[8], v8[8];
#pragma unroll
            for (int e = 0; e < 8; ++e) {
                q8[e] = __shfl_sync(0xffffffffu, qf, e, 8);
                k8[e] = __shfl_sync(0xffffffffu, kf, e, 8);
                v8[e] = __shfl_sync(0xffffffffu, vf, e, 8);
            }
            float s00 = 0.f, s01 = 0.f, s10 = 0.f, s11 = 0.f;
#pragma unroll
            for (int h = 0; h < 4; ++h) {
                float q0 = q8[2 * h], q1 = q8[2 * h + 1];
                float k0 = k8[2 * h], k1 = k8[2 * h + 1];
                s00 = fmaf(q0, k0, s00); s01 = fmaf(q0, k1, s01);
                s10 = fmaf(q1, k0, s10); s11 = fmaf(q1, k1, s11);
            }
            const float is2 = 0.70710678118654752440f;
            s00 *= is2; s01 *= is2; s10 *= is2; s11 *= is2;
            float m0 = fmaxf(s00, s01);
            float e00 = expf(s00 - m0), e01 = expf(s01 - m0);
            float n0 = 1.f / (e00 + e01);
            float a00 = e00 * n0, a01 = e01 * n0;
            float m1 = fmaxf(s10, s11);
            float e10 = expf(s10 - m1), e11 = expf(s11 - m1);
            float n1 = 1.f / (e10 + e11);
            float a10 = e10 * n1, a11 = e11 * n1;

            float att[8];
#pragma unroll
            for (int h = 0; h < 4; ++h) {
                att[2 * h]     = fmaf(a00, v8[2 * h], a01 * v8[2 * h + 1]);
                att[2 * h + 1] = fmaf(a10, v8[2 * h], a11 * v8[2 * h + 1]);
            }
            float aggf = __ldg(wob + g * 8 + f);
            const float* wor = wo + (size_t)(g * 8 + f) * 8;
#pragma unroll
            for (int e = 0; e < 8; ++e)
                aggf = fmaf(att[e], __ldg(wor + e), aggf);

            pred = fmaf(rw, aggf, pred);
        }
        if (L == 0) out[OFF_PRED + n] = pred;
    }
}

// ---------------------------------------------------------------------------
extern "C" void kernel_launch(void* const* d_in, const int* in_sizes, int n_in,
                              void* d_out, int out_size)
{
    const float* price = (const float*)d_in[0];
    const float* news  = (const float*)d_in[1];
    const float* mask  = (const float*)d_in[2];
    const float* rW    = (const float*)d_in[3];
    const float* rb    = (const float*)d_in[4];
    const float* gW    = (const float*)d_in[5];
    const float* gb    = (const float*)d_in[6];
    const float* eW    = (const float*)d_in[7];
    const float* eb    = (const float*)d_in[8];
    const float* wq    = (const float*)d_in[9];
    const float* wqb   = (const float*)d_in[10];
    const float* wk    = (const float*)d_in[11];
    const float* wkb   = (const float*)d_in[12];
    const float* wv    = (const float*)d_in[13];
    const float* wvb   = (const float*)d_in[14];
    const float* wo    = (const float*)d_in[15];
    const float* wob   = (const float*)d_in[16];
    float* out = (float*)d_out;

    k_agg<<<NROWS + (XLD * 128) / 256, 256>>>(price, news, mask, rW);
    k_main<<<NROWS / RPB, 256>>>(rb, gW, gb, eW, eb,
                                 wq, wqb, wk, wkb, wv, wvb, wo, wob, out);
}